// round 2
// baseline (speedup 1.0000x reference)
#include <cuda_runtime.h>
#include <cstdint>

#define NB 16384
#define NC 4
#define NH 8
#define NT 120
#define ALPHA 0.2f

// XLA f32 tanh: rational approximation (matches jnp.tanh lowering).
__device__ __forceinline__ float tanh_xla(float x) {
    const float kClamp = 7.90531110763549805f;
    float xc = fminf(fmaxf(x, -kClamp), kClamp);
    float x2 = xc * xc;
    float p = -2.76076847742355e-16f;
    p = fmaf(p, x2,  2.00018790482477e-13f);
    p = fmaf(p, x2, -8.60467152213735e-11f);
    p = fmaf(p, x2,  5.12229709037114e-08f);
    p = fmaf(p, x2,  1.48572235717979e-05f);
    p = fmaf(p, x2,  6.37261928875436e-04f);
    p = fmaf(p, x2,  4.89352455891786e-03f);
    p = xc * p;
    float q = 1.19825839466702e-06f;
    q = fmaf(q, x2, 1.18534705686654e-04f);
    q = fmaf(q, x2, 2.26843463243900e-03f);
    q = fmaf(q, x2, 4.89352518554385e-03f);
    float r = p / q;
    return (fabsf(x) < 0.0004f) ? x : r;
}

__global__ void __launch_bounds__(128)
accum_rnn_kernel(const float* __restrict__ logits,
                 const float* __restrict__ input_scale,
                 const float* __restrict__ noise_std,
                 const float* __restrict__ input_proj_w,   // [H,1]
                 const float* __restrict__ input_proj_b,   // [H]
                 const float* __restrict__ self_proj_w,    // [H,H], W[k][h]
                 const float* __restrict__ comp_proj_w,    // [H,1]
                 const float* __restrict__ evidence_w,     // [1,H]
                 const float* __restrict__ evidence_b,     // [1]
                 const float* __restrict__ class_bias,     // [C,H]
                 const float* __restrict__ competition,    // [C,C]
                 const float* __restrict__ noise,          // [T,B,C,H]
                 float* __restrict__ out)                  // [B,C]
{
    int tid = blockIdx.x * blockDim.x + threadIdx.x;   // 0..B*C-1
    if (tid >= NB * NC) return;
    int b = tid >> 2;
    int c = tid & 3;

    float scale = __ldg(input_scale);
    float nstd  = __ldg(noise_std);
    float evb   = __ldg(evidence_b);

    // Weights into registers (broadcast loads, L2/L1 hits)
    float W[NH][NH];
    #pragma unroll
    for (int k = 0; k < NH; k++)
        #pragma unroll
        for (int h = 0; h < NH; h++)
            W[k][h] = __ldg(&self_proj_w[k * NH + h]);

    float evw[NH], cpw[NH];
    #pragma unroll
    for (int h = 0; h < NH; h++) {
        evw[h] = __ldg(&evidence_w[h]);
        cpw[h] = __ldg(&comp_proj_w[h]);
    }

    float compcol[NC];  // competition[k][c] for my class column
    #pragma unroll
    for (int k = 0; k < NC; k++)
        compcol[k] = __ldg(&competition[k * NC + c]);

    // Input embedding for this (b,c): relu(logit*scale)*ipw[h] + ipb[h] + class_bias[c,h]
    float li = fmaxf(__ldg(&logits[b * NC + c]) * scale, 0.0f);
    float inp[NH];
    #pragma unroll
    for (int h = 0; h < NH; h++)
        inp[h] = fmaf(li, __ldg(&input_proj_w[h]),
                      __ldg(&input_proj_b[h]) + __ldg(&class_bias[c * NH + h]));

    float state[NH];
    #pragma unroll
    for (int h = 0; h < NH; h++) state[h] = 0.0f;

    float ev = evb;      // evidence of zero state
    int first_t = NT;    // NT == never crossed

    const unsigned FULL = 0xffffffffu;
    int base_lane = (threadIdx.x & 31) & ~3;  // lane of class-0 sibling

    // noise base for (b,c); per-t stride = B*C*H floats
    const float4* nbase = reinterpret_cast<const float4*>(
        noise + ((size_t)b * NC + c) * NH);
    const size_t t_stride4 = (size_t)NB * NC * NH / 4;   // in float4 units

    #pragma unroll 1
    for (int t = 0; t < NT; t++) {
        // noise for this step (2x float4 = 8 floats), issued early
        float4 n0 = __ldg(nbase + (size_t)t * t_stride4);
        float4 n1 = __ldg(nbase + (size_t)t * t_stride4 + 1);

        // competition term: comp[c] = sum_k ev_k * competition[k][c]
        float comp = 0.0f;
        #pragma unroll
        for (int k = 0; k < NC; k++) {
            float evk = __shfl_sync(FULL, ev, base_lane + k);
            comp = fmaf(evk, compcol[k], comp);
        }

        // pre-activation: acc[k] = sum_h state[h]*W[k][h] + inp[k] + comp*cpw[k] + n[k]*std
        float acc[NH];
        #pragma unroll
        for (int k = 0; k < NH; k++) acc[k] = inp[k];
        #pragma unroll
        for (int h = 0; h < NH; h++) {
            float sh = state[h];
            #pragma unroll
            for (int k = 0; k < NH; k++)
                acc[k] = fmaf(sh, W[k][h], acc[k]);
        }
        float nn[NH] = {n0.x, n0.y, n0.z, n0.w, n1.x, n1.y, n1.z, n1.w};
        #pragma unroll
        for (int k = 0; k < NH; k++) {
            acc[k] = fmaf(comp, cpw[k], acc[k]);
            acc[k] = fmaf(nn[k], nstd, acc[k]);
        }

        // cand = tanh(acc); state += ALPHA*(cand - state)
        #pragma unroll
        for (int k = 0; k < NH; k++) {
            float cand = tanh_xla(acc[k]);
            state[k] = fmaf(ALPHA, cand - state[k], state[k]);
        }

        // new evidence
        float e = evb;
        #pragma unroll
        for (int h = 0; h < NH; h++)
            e = fmaf(state[h], evw[h], e);
        ev = e;

        // first crossing (strictly > threshold 0.5)
        if (first_t == NT && e > 0.5f) first_t = t;
    }

    out[tid] = (first_t < NT) ? ((float)(first_t + 1) * 10.0f) / 1000.0f
                              : (((float)NT * 10.0f) / 1000.0f);
}

extern "C" void kernel_launch(void* const* d_in, const int* in_sizes, int n_in,
                              void* d_out, int out_size) {
    const float* logits       = (const float*)d_in[0];
    const float* input_scale  = (const float*)d_in[1];
    const float* noise_std    = (const float*)d_in[2];
    const float* input_proj_w = (const float*)d_in[3];
    const float* input_proj_b = (const float*)d_in[4];
    const float* self_proj_w  = (const float*)d_in[5];
    const float* comp_proj_w  = (const float*)d_in[6];
    const float* evidence_w   = (const float*)d_in[7];
    const float* evidence_b   = (const float*)d_in[8];
    const float* class_bias   = (const float*)d_in[9];
    const float* competition  = (const float*)d_in[10];
    const float* noise        = (const float*)d_in[11];
    float* out = (float*)d_out;

    int total = NB * NC;
    int threads = 128;
    int blocks = (total + threads - 1) / threads;
    accum_rnn_kernel<<<blocks, threads>>>(
        logits, input_scale, noise_std, input_proj_w, input_proj_b,
        self_proj_w, comp_proj_w, evidence_w, evidence_b,
        class_bias, competition, noise, out);
}

// round 4
// speedup vs baseline: 1.0148x; 1.0148x over previous
#include <cuda_runtime.h>
#include <cstdint>

#define NB 16384
#define NC 4
#define NH 8
#define NT 120
#define ALPHA 0.2f

// XLA f32 tanh: rational approximation (matches jnp.tanh lowering).
__device__ __forceinline__ float tanh_xla(float x) {
    const float kClamp = 7.90531110763549805f;
    float xc = fminf(fmaxf(x, -kClamp), kClamp);
    float x2 = xc * xc;
    float p = -2.76076847742355e-16f;
    p = fmaf(p, x2,  2.00018790482477e-13f);
    p = fmaf(p, x2, -8.60467152213735e-11f);
    p = fmaf(p, x2,  5.12229709037114e-08f);
    p = fmaf(p, x2,  1.48572235717979e-05f);
    p = fmaf(p, x2,  6.37261928875436e-04f);
    p = fmaf(p, x2,  4.89352455891786e-03f);
    p = xc * p;
    float q = 1.19825839466702e-06f;
    q = fmaf(q, x2, 1.18534705686654e-04f);
    q = fmaf(q, x2, 2.26843463243900e-03f);
    q = fmaf(q, x2, 4.89352518554385e-03f);
    float r = p / q;
    return (fabsf(x) < 0.0004f) ? x : r;
}

__global__ void __launch_bounds__(128)
accum_rnn_kernel(const float* __restrict__ logits,
                 const float* __restrict__ input_scale,
                 const float* __restrict__ noise_std,
                 const float* __restrict__ input_proj_w,   // [H,1]
                 const float* __restrict__ input_proj_b,   // [H]
                 const float* __restrict__ self_proj_w,    // [H,H], W[k][h]
                 const float* __restrict__ comp_proj_w,    // [H,1]
                 const float* __restrict__ evidence_w,     // [1,H]
                 const float* __restrict__ evidence_b,     // [1]
                 const float* __restrict__ class_bias,     // [C,H]
                 const float* __restrict__ competition,    // [C,C]
                 const float* __restrict__ noise,          // [T,B,C,H]
                 float* __restrict__ out)                  // [B,C]
{
    int tid = blockIdx.x * blockDim.x + threadIdx.x;   // 0..B*C-1
    if (tid >= NB * NC) return;
    int b = tid >> 2;
    int c = tid & 3;

    float scale = __ldg(input_scale);
    float nstd  = __ldg(noise_std);
    float evb   = __ldg(evidence_b);

    // Weights into registers (broadcast loads, L2/L1 hits)
    float W[NH][NH];
    #pragma unroll
    for (int k = 0; k < NH; k++)
        #pragma unroll
        for (int h = 0; h < NH; h++)
            W[k][h] = __ldg(&self_proj_w[k * NH + h]);

    float evw[NH], cpw[NH];
    #pragma unroll
    for (int h = 0; h < NH; h++) {
        evw[h] = __ldg(&evidence_w[h]);
        cpw[h] = __ldg(&comp_proj_w[h]);
    }

    float compcol[NC];  // competition[k][c] for my class column
    #pragma unroll
    for (int k = 0; k < NC; k++)
        compcol[k] = __ldg(&competition[k * NC + c]);

    // Input embedding for this (b,c): relu(logit*scale)*ipw[h] + ipb[h] + class_bias[c,h]
    float li = fmaxf(__ldg(&logits[b * NC + c]) * scale, 0.0f);
    float inp[NH];
    #pragma unroll
    for (int h = 0; h < NH; h++)
        inp[h] = fmaf(li, __ldg(&input_proj_w[h]),
                      __ldg(&input_proj_b[h]) + __ldg(&class_bias[c * NH + h]));

    float state[NH];
    #pragma unroll
    for (int h = 0; h < NH; h++) state[h] = 0.0f;

    float ev = evb;      // evidence of zero state
    int first_t = NT;    // NT == never crossed

    const unsigned FULL = 0xffffffffu;
    int base_lane = (threadIdx.x & 31) & ~3;  // lane of class-0 sibling

    // noise base for (b,c); per-t stride = B*C*H floats
    const float4* nbase = reinterpret_cast<const float4*>(
        noise + ((size_t)b * NC + c) * NH);
    const size_t t_stride4 = (size_t)NB * NC * NH / 4;   // in float4 units

    #pragma unroll 1
    for (int t = 0; t < NT; t++) {
        // noise for this step (2x float4 = 8 floats), issued early
        float4 n0 = __ldg(nbase + (size_t)t * t_stride4);
        float4 n1 = __ldg(nbase + (size_t)t * t_stride4 + 1);

        // competition term: comp[c] = sum_k ev_k * competition[k][c]
        float comp = 0.0f;
        #pragma unroll
        for (int k = 0; k < NC; k++) {
            float evk = __shfl_sync(FULL, ev, base_lane + k);
            comp = fmaf(evk, compcol[k], comp);
        }

        // pre-activation: acc[k] = sum_h state[h]*W[k][h] + inp[k] + comp*cpw[k] + n[k]*std
        float acc[NH];
        #pragma unroll
        for (int k = 0; k < NH; k++) acc[k] = inp[k];
        #pragma unroll
        for (int h = 0; h < NH; h++) {
            float sh = state[h];
            #pragma unroll
            for (int k = 0; k < NH; k++)
                acc[k] = fmaf(sh, W[k][h], acc[k]);
        }
        float nn[NH] = {n0.x, n0.y, n0.z, n0.w, n1.x, n1.y, n1.z, n1.w};
        #pragma unroll
        for (int k = 0; k < NH; k++) {
            acc[k] = fmaf(comp, cpw[k], acc[k]);
            acc[k] = fmaf(nn[k], nstd, acc[k]);
        }

        // cand = tanh(acc); state += ALPHA*(cand - state)
        #pragma unroll
        for (int k = 0; k < NH; k++) {
            float cand = tanh_xla(acc[k]);
            state[k] = fmaf(ALPHA, cand - state[k], state[k]);
        }

        // new evidence
        float e = evb;
        #pragma unroll
        for (int h = 0; h < NH; h++)
            e = fmaf(state[h], evw[h], e);
        ev = e;

        // first crossing (strictly > threshold 0.5)
        if (first_t == NT && e > 0.5f) first_t = t;
    }

    out[tid] = (first_t < NT) ? ((float)(first_t + 1) * 10.0f) / 1000.0f
                              : (((float)NT * 10.0f) / 1000.0f);
}

extern "C" void kernel_launch(void* const* d_in, const int* in_sizes, int n_in,
                              void* d_out, int out_size) {
    const float* logits       = (const float*)d_in[0];
    const float* input_scale  = (const float*)d_in[1];
    const float* noise_std    = (const float*)d_in[2];
    const float* input_proj_w = (const float*)d_in[3];
    const float* input_proj_b = (const float*)d_in[4];
    const float* self_proj_w  = (const float*)d_in[5];
    const float* comp_proj_w  = (const float*)d_in[6];
    const float* evidence_w   = (const float*)d_in[7];
    const float* evidence_b   = (const float*)d_in[8];
    const float* class_bias   = (const float*)d_in[9];
    const float* competition  = (const float*)d_in[10];
    const float* noise        = (const float*)d_in[11];
    float* out = (float*)d_out;

    int total = NB * NC;
    int threads = 128;
    int blocks = (total + threads - 1) / threads;
    accum_rnn_kernel<<<blocks, threads>>>(
        logits, input_scale, noise_std, input_proj_w, input_proj_b,
        self_proj_w, comp_proj_w, evidence_w, evidence_b,
        class_bias, competition, noise, out);
}